// round 14
// baseline (speedup 1.0000x reference)
#include <cuda_runtime.h>
#include <cuda_bf16.h>
#include <cstdint>

#define M_NODES 100000
#define K_DIM   256
#define N_DIM   128
#define N_EDGES 1600000

#define SCAN_N   100352            // M_NODES padded to 392*256
#define SCAN_BLK 392

// Intermediate h = x @ W (fp32), L2-resident during gather.
__device__ float g_h[(size_t)M_NODES * N_DIM];
// Pre-split, pre-transposed weights: [N=128][K=256] bf16, K-major.
__device__ __nv_bfloat16 g_Wt_hi[(size_t)N_DIM * K_DIM];
__device__ __nv_bfloat16 g_Wt_lo[(size_t)N_DIM * K_DIM];
// CSR scratch
__device__ int      g_count[SCAN_N];
__device__ int      g_off[SCAN_N];
__device__ int      g_slot[N_EDGES];  // edge's slot within its row (from count pass)
__device__ int      g_total;
__device__ uint64_t g_csr[N_EDGES];   // packed {val_bits:32 | col:32}

__device__ __forceinline__ uint32_t smem_u32(const void* p) {
    uint32_t a;
    asm("{ .reg .u64 t; cvta.to.shared.u64 t, %1; cvt.u32.u64 %0, t; }" : "=r"(a) : "l"(p));
    return a;
}
#define SW128(off) ((off) ^ (((off) >> 3) & 0x70))

// ---------------------------------------------------------------------------
// W pre-split: g_Wt_{hi,lo}[n][k] = split(W[k][n])
// ---------------------------------------------------------------------------
__global__ void wconv_kernel(const float* __restrict__ W) {
    int idx = blockIdx.x * blockDim.x + threadIdx.x;   // 0..32767
    int n = idx >> 8, k = idx & 255;
    float w = W[(size_t)k * N_DIM + n];
    __nv_bfloat16 hi = __float2bfloat16_rn(w);
    __nv_bfloat16 lo = __float2bfloat16_rn(w - __bfloat162float(hi));
    g_Wt_hi[idx] = hi;
    g_Wt_lo[idx] = lo;
}

// ---------------------------------------------------------------------------
// mma.sync bf16 GEMM, CTA tile M128xN128, K chunk 64, 3-term split.
// R12: software-pipelined x loads (next chunk prefetched to registers
// during MMA of current chunk).
// ---------------------------------------------------------------------------
#define KC 64
#define SA_HI 0
#define SA_LO 16384
#define SB_HI 32768
#define SB_LO 49152
#define SMEM_TOTAL 65536

__device__ __forceinline__ void ldsm_x4(uint32_t& r0, uint32_t& r1,
                                        uint32_t& r2, uint32_t& r3, uint32_t addr) {
    asm volatile("ldmatrix.sync.aligned.m8n8.x4.shared.b16 {%0,%1,%2,%3}, [%4];"
                 : "=r"(r0), "=r"(r1), "=r"(r2), "=r"(r3) : "r"(addr));
}
__device__ __forceinline__ void mma_bf16(float* c, const uint32_t* a, const uint32_t* b) {
    asm volatile("mma.sync.aligned.m16n8k16.row.col.f32.bf16.bf16.f32 "
                 "{%0,%1,%2,%3}, {%4,%5,%6,%7}, {%8,%9}, {%0,%1,%2,%3};"
                 : "+f"(c[0]), "+f"(c[1]), "+f"(c[2]), "+f"(c[3])
                 : "r"(a[0]), "r"(a[1]), "r"(a[2]), "r"(a[3]), "r"(b[0]), "r"(b[1]));
}

__global__ __launch_bounds__(256, 2) void gemm_mma_kernel(const float* __restrict__ x) {
    extern __shared__ char smem[];
    const uint32_t sb = smem_u32(smem);
    const int tid  = threadIdx.x;
    const int wid  = tid >> 5;
    const int lane = tid & 31;
    const int row0 = blockIdx.x * 128;

    const int wm = wid & 1;
    const int wn = wid >> 1;

    const int lr = tid >> 1;
    const int lh = tid & 1;
    int grow_ld = row0 + lr;
    if (grow_ld >= M_NODES) grow_ld = 0;   // clamp: finite garbage, discarded at store
    const float4* __restrict__ xrow = (const float4*)(x + (size_t)grow_ld * K_DIM);
    const uint4* __restrict__ wt_hi = (const uint4*)g_Wt_hi;
    const uint4* __restrict__ wt_lo = (const uint4*)g_Wt_lo;

    const int a_row = wm * 64 + (lane & 15);
    const int a_kbl = (lane & 16);
    const int b_row = wn * 32 + (lane & 7) + ((lane & 16) ? 8 : 0);
    const int b_kbl = (lane & 8) ? 16 : 0;

    float acc[4][4][4];
#pragma unroll
    for (int mi = 0; mi < 4; mi++)
#pragma unroll
        for (int ni = 0; ni < 4; ni++)
#pragma unroll
            for (int i = 0; i < 4; i++) acc[mi][ni][i] = 0.f;

    // Prologue: prefetch chunk 0 (this thread's 32 floats).
    float4 fr[8];
    {
        const float4* xr = xrow + ((lh * 32) >> 2);
#pragma unroll
        for (int j = 0; j < 8; j++) fr[j] = xr[j];
    }

    for (int c = 0; c < K_DIM / KC; c++) {
        const int k0 = c * KC;
        // ---- Convert prefetched A chunk -> bf16 hi/lo, store swizzled ----
        {
            const float* f = (const float*)fr;
#pragma unroll
            for (int j = 0; j < 4; j++) {
                uint32_t ph[4], pl[4];
#pragma unroll
                for (int i = 0; i < 4; i++) {
                    float f0 = f[j * 8 + 2 * i], f1 = f[j * 8 + 2 * i + 1];
                    __nv_bfloat16 h0 = __float2bfloat16_rn(f0);
                    __nv_bfloat16 h1 = __float2bfloat16_rn(f1);
                    __nv_bfloat162 hp = __halves2bfloat162(h0, h1);
                    __nv_bfloat162 lp = __halves2bfloat162(
                        __float2bfloat16_rn(f0 - __bfloat162float(h0)),
                        __float2bfloat16_rn(f1 - __bfloat162float(h1)));
                    ph[i] = *(uint32_t*)&hp;
                    pl[i] = *(uint32_t*)&lp;
                }
                uint32_t off = SW128((uint32_t)(lr * 128 + lh * 64 + j * 16));
                *(uint4*)(smem + SA_HI + off) = make_uint4(ph[0], ph[1], ph[2], ph[3]);
                *(uint4*)(smem + SA_LO + off) = make_uint4(pl[0], pl[1], pl[2], pl[3]);
            }
        }
        // ---- B tiles (L2-resident after first wave) ----
        {
            const int gbase = (lr * K_DIM + k0 + lh * 32) >> 3;
#pragma unroll
            for (int j = 0; j < 4; j++) {
                uint32_t off = SW128((uint32_t)(lr * 128 + lh * 64 + j * 16));
                *(uint4*)(smem + SB_HI + off) = wt_hi[gbase + j];
                *(uint4*)(smem + SB_LO + off) = wt_lo[gbase + j];
            }
        }
        __syncthreads();

        // ---- Prefetch next chunk's x into registers (hidden under MMA) ----
        if (c + 1 < K_DIM / KC) {
            const float4* xr = xrow + (((c + 1) * KC + lh * 32) >> 2);
#pragma unroll
            for (int j = 0; j < 8; j++) fr[j] = xr[j];
        }

        // ---- Compute: 4 k16 steps ----
#pragma unroll
        for (int ks = 0; ks < 4; ks++) {
            const int kbase = ks * 32;
            uint32_t bh[8], bl[8];
#pragma unroll
            for (int g = 0; g < 2; g++) {
                uint32_t off = SW128((uint32_t)((b_row + g * 16) * 128 + kbase + b_kbl));
                ldsm_x4(bh[g * 4 + 0], bh[g * 4 + 1], bh[g * 4 + 2], bh[g * 4 + 3],
                        sb + SB_HI + off);
                ldsm_x4(bl[g * 4 + 0], bl[g * 4 + 1], bl[g * 4 + 2], bl[g * 4 + 3],
                        sb + SB_LO + off);
            }
#pragma unroll
            for (int mi = 0; mi < 4; mi++) {
                uint32_t ah[4], al[4];
                uint32_t off = SW128((uint32_t)((a_row + mi * 16) * 128 + kbase + a_kbl));
                ldsm_x4(ah[0], ah[1], ah[2], ah[3], sb + SA_HI + off);
                ldsm_x4(al[0], al[1], al[2], al[3], sb + SA_LO + off);
#pragma unroll
                for (int ni = 0; ni < 4; ni++) {
                    mma_bf16(acc[mi][ni], ah, &bh[ni * 2]);
                    mma_bf16(acc[mi][ni], ah, &bl[ni * 2]);
                    mma_bf16(acc[mi][ni], al, &bh[ni * 2]);
                }
            }
        }
        __syncthreads();
    }

    const int er = lane >> 2;
    const int ec = (lane & 3) * 2;
#pragma unroll
    for (int mi = 0; mi < 4; mi++) {
        int grow = row0 + wm * 64 + mi * 16 + er;
#pragma unroll
        for (int ni = 0; ni < 4; ni++) {
            int col = wn * 32 + ni * 8 + ec;
            if (grow < M_NODES)
                *(float2*)(g_h + (size_t)grow * N_DIM + col) =
                    make_float2(acc[mi][ni][0], acc[mi][ni][1]);
            if (grow + 8 < M_NODES)
                *(float2*)(g_h + (size_t)(grow + 8) * N_DIM + col) =
                    make_float2(acc[mi][ni][2], acc[mi][ni][3]);
        }
    }
}

// ---------------------------------------------------------------------------
// CSR build: zero -> count(+slot) -> fused scan -> fill (atomic-free)
// ---------------------------------------------------------------------------
__global__ __launch_bounds__(256) void zero_kernel() {
    int i = blockIdx.x * blockDim.x + threadIdx.x;
    g_count[i] = 0;
    if (i == 0) g_total = 0;
}

// 4 edges per thread; slot = position of edge within its row.
__global__ __launch_bounds__(256) void count_kernel(const int* __restrict__ rows) {
    int i0 = (blockIdx.x * blockDim.x + threadIdx.x) * 4;
    if (i0 + 3 < N_EDGES) {
        int4 r4 = *(const int4*)(rows + i0);
        g_slot[i0 + 0] = atomicAdd(&g_count[r4.x], 1);
        g_slot[i0 + 1] = atomicAdd(&g_count[r4.y], 1);
        g_slot[i0 + 2] = atomicAdd(&g_count[r4.z], 1);
        g_slot[i0 + 3] = atomicAdd(&g_count[r4.w], 1);
    } else {
        for (int j = 0; j < 4 && i0 + j < N_EDGES; j++)
            g_slot[i0 + j] = atomicAdd(&g_count[rows[i0 + j]], 1);
    }
}

// Single-pass scan: block-local inclusive scan + atomic block base.
// CSR ranges are disjoint (ordering across blocks irrelevant for gather).
__global__ __launch_bounds__(256) void scan_fused_kernel() {
    __shared__ int s[256];
    __shared__ int base_sh;
    int t = threadIdx.x, b = blockIdx.x;
    int i = b * 256 + t;
    int c = g_count[i];
    s[t] = c;
    __syncthreads();
    int v = c;
#pragma unroll
    for (int d = 1; d < 256; d <<= 1) {
        int add = (t >= d) ? s[t - d] : 0;
        __syncthreads();
        v += add;
        s[t] = v;
        __syncthreads();
    }
    if (t == 255) base_sh = atomicAdd(&g_total, v);
    __syncthreads();
    g_off[i] = base_sh + v - c;      // exclusive within block + block base
}

// Atomic-free fill: pos = off[row] + slot[edge]. 4 edges per thread, MLP 4.
__global__ __launch_bounds__(256) void fill_kernel(const int* __restrict__ rows,
                                                   const int* __restrict__ cols,
                                                   const float* __restrict__ vals) {
    int i0 = (blockIdx.x * blockDim.x + threadIdx.x) * 4;
    if (i0 + 3 < N_EDGES) {
        int4   r4 = *(const int4*)(rows + i0);
        int4   c4 = *(const int4*)(cols + i0);
        float4 v4 = *(const float4*)(vals + i0);
        int4   s4 = *(const int4*)(g_slot + i0);
        int o0 = g_off[r4.x], o1 = g_off[r4.y], o2 = g_off[r4.z], o3 = g_off[r4.w];
        g_csr[o0 + s4.x] = ((uint64_t)__float_as_uint(v4.x) << 32) | (uint32_t)c4.x;
        g_csr[o1 + s4.y] = ((uint64_t)__float_as_uint(v4.y) << 32) | (uint32_t)c4.y;
        g_csr[o2 + s4.z] = ((uint64_t)__float_as_uint(v4.z) << 32) | (uint32_t)c4.z;
        g_csr[o3 + s4.w] = ((uint64_t)__float_as_uint(v4.w) << 32) | (uint32_t)c4.w;
    } else {
        for (int j = 0; j < 4 && i0 + j < N_EDGES; j++) {
            int i = i0 + j;
            int pos = g_off[rows[i]] + g_slot[i];
            g_csr[pos] = ((uint64_t)__float_as_uint(vals[i]) << 32) | (uint32_t)cols[i];
        }
    }
}

// ---------------------------------------------------------------------------
// Gather: one warp per node, smem edge broadcast, x4 unroll, fused relu.
// (at L2 traffic floor — unchanged)
// ---------------------------------------------------------------------------
__global__ __launch_bounds__(256) void gather_kernel(float* __restrict__ out) {
    __shared__ uint64_t ebuf[8][32];
    const int wib  = threadIdx.x >> 5;
    const int lane = threadIdx.x & 31;
    const int warp = (blockIdx.x * blockDim.x + threadIdx.x) >> 5;
    if (warp >= M_NODES) return;

    const int start = g_off[warp];
    const int deg   = g_count[warp];
    const float4* __restrict__ h4 = (const float4*)g_h;

    float4 acc0 = make_float4(0.f, 0.f, 0.f, 0.f);
    float4 acc1 = make_float4(0.f, 0.f, 0.f, 0.f);

    for (int base = 0; base < deg; base += 32) {
        int lim = deg - base;
        if (lim > 32) lim = 32;
        __syncwarp();
        if (lane < lim) ebuf[wib][lane] = g_csr[start + base + lane];
        __syncwarp();

        int j = 0;
        for (; j + 4 <= lim; j += 4) {
            uint64_t e0 = ebuf[wib][j + 0];
            uint64_t e1 = ebuf[wib][j + 1];
            uint64_t e2 = ebuf[wib][j + 2];
            uint64_t e3 = ebuf[wib][j + 3];
            float4 h0 = h4[(size_t)(uint32_t)e0 * 32 + lane];
            float4 h1 = h4[(size_t)(uint32_t)e1 * 32 + lane];
            float4 h2 = h4[(size_t)(uint32_t)e2 * 32 + lane];
            float4 h3 = h4[(size_t)(uint32_t)e3 * 32 + lane];
            float v0 = __uint_as_float((uint32_t)(e0 >> 32));
            float v1 = __uint_as_float((uint32_t)(e1 >> 32));
            float v2 = __uint_as_float((uint32_t)(e2 >> 32));
            float v3 = __uint_as_float((uint32_t)(e3 >> 32));
            acc0.x = fmaf(v0, h0.x, acc0.x); acc0.y = fmaf(v0, h0.y, acc0.y);
            acc0.z = fmaf(v0, h0.z, acc0.z); acc0.w = fmaf(v0, h0.w, acc0.w);
            acc1.x = fmaf(v1, h1.x, acc1.x); acc1.y = fmaf(v1, h1.y, acc1.y);
            acc1.z = fmaf(v1, h1.z, acc1.z); acc1.w = fmaf(v1, h1.w, acc1.w);
            acc0.x = fmaf(v2, h2.x, acc0.x); acc0.y = fmaf(v2, h2.y, acc0.y);
            acc0.z = fmaf(v2, h2.z, acc0.z); acc0.w = fmaf(v2, h2.w, acc0.w);
            acc1.x = fmaf(v3, h3.x, acc1.x); acc1.y = fmaf(v3, h3.y, acc1.y);
            acc1.z = fmaf(v3, h3.z, acc1.z); acc1.w = fmaf(v3, h3.w, acc1.w);
        }
        for (; j < lim; j++) {
            uint64_t e = ebuf[wib][j];
            float4 hv = h4[(size_t)(uint32_t)e * 32 + lane];
            float  v  = __uint_as_float((uint32_t)(e >> 32));
            acc0.x = fmaf(v, hv.x, acc0.x); acc0.y = fmaf(v, hv.y, acc0.y);
            acc0.z = fmaf(v, hv.z, acc0.z); acc0.w = fmaf(v, hv.w, acc0.w);
        }
    }

    float4 r;
    r.x = fmaxf(acc0.x + acc1.x, 0.f);
    r.y = fmaxf(acc0.y + acc1.y, 0.f);
    r.z = fmaxf(acc0.z + acc1.z, 0.f);
    r.w = fmaxf(acc0.w + acc1.w, 0.f);
    *(float4*)(out + (size_t)warp * N_DIM + lane * 4) = r;
}

extern "C" void kernel_launch(void* const* d_in, const int* in_sizes, int n_in,
                              void* d_out, int out_size) {
    const float* x    = (const float*)d_in[0];
    const float* W    = (const float*)d_in[1];
    const int*   rows = (const int*)d_in[2];
    const int*   cols = (const int*)d_in[3];
    const float* vals = (const float*)d_in[4];
    float* out = (float*)d_out;

    cudaFuncSetAttribute(gemm_mma_kernel,
                         cudaFuncAttributeMaxDynamicSharedMemorySize, SMEM_TOTAL);

    // CSR build
    zero_kernel<<<SCAN_BLK, 256>>>();
    count_kernel<<<(N_EDGES / 4 + 255) / 256, 256>>>(rows);
    scan_fused_kernel<<<SCAN_BLK, 256>>>();
    fill_kernel<<<(N_EDGES / 4 + 255) / 256, 256>>>(rows, cols, vals);

    // Dense projection h = x @ W
    wconv_kernel<<<(N_DIM * K_DIM) / 256, 256>>>(W);
    gemm_mma_kernel<<<(M_NODES + 127) / 128, 256, SMEM_TOTAL>>>(x);

    // Aggregate + relu, single write per row
    gather_kernel<<<(M_NODES * 32 + 255) / 256, 256>>>(out);
}

// round 15
// speedup vs baseline: 1.0483x; 1.0483x over previous
#include <cuda_runtime.h>
#include <cuda_bf16.h>
#include <cstdint>

#define M_NODES 100000
#define K_DIM   256
#define N_DIM   128
#define N_EDGES 1600000

#define SCAN_N   100352            // M_NODES padded to 392*256
#define SCAN_BLK 392

// Intermediate h = x @ W (fp32), L2-resident during gather.
__device__ float g_h[(size_t)M_NODES * N_DIM];
// Pre-split, pre-transposed weights: [N=128][K=256] bf16, K-major.
__device__ __nv_bfloat16 g_Wt_hi[(size_t)N_DIM * K_DIM];
__device__ __nv_bfloat16 g_Wt_lo[(size_t)N_DIM * K_DIM];
// CSR scratch
__device__ int      g_count[SCAN_N];
__device__ int      g_off[SCAN_N];
__device__ int      g_slot[N_EDGES];  // edge's slot within its row (from count pass)
__device__ int      g_total;
__device__ uint64_t g_csr[N_EDGES];   // packed {val_bits:32 | col:32}

__device__ __forceinline__ uint32_t smem_u32(const void* p) {
    uint32_t a;
    asm("{ .reg .u64 t; cvta.to.shared.u64 t, %1; cvt.u32.u64 %0, t; }" : "=r"(a) : "l"(p));
    return a;
}
#define SW128(off) ((off) ^ (((off) >> 3) & 0x70))

// ---------------------------------------------------------------------------
// W pre-split: g_Wt_{hi,lo}[n][k] = split(W[k][n])
// ---------------------------------------------------------------------------
__global__ void wconv_kernel(const float* __restrict__ W) {
    int idx = blockIdx.x * blockDim.x + threadIdx.x;   // 0..32767
    int n = idx >> 8, k = idx & 255;
    float w = W[(size_t)k * N_DIM + n];
    __nv_bfloat16 hi = __float2bfloat16_rn(w);
    __nv_bfloat16 lo = __float2bfloat16_rn(w - __bfloat162float(hi));
    g_Wt_hi[idx] = hi;
    g_Wt_lo[idx] = lo;
}

// ---------------------------------------------------------------------------
// mma.sync bf16 GEMM, CTA tile M128xN128, K chunk 64, 3-term split.
// R15: reverted to R11 structure -- short-range load->convert window.
// (R12's cross-MMA register prefetch forced spills under the 128-reg cap.)
// ---------------------------------------------------------------------------
#define KC 64
#define SA_HI 0
#define SA_LO 16384
#define SB_HI 32768
#define SB_LO 49152
#define SMEM_TOTAL 65536

__device__ __forceinline__ void ldsm_x4(uint32_t& r0, uint32_t& r1,
                                        uint32_t& r2, uint32_t& r3, uint32_t addr) {
    asm volatile("ldmatrix.sync.aligned.m8n8.x4.shared.b16 {%0,%1,%2,%3}, [%4];"
                 : "=r"(r0), "=r"(r1), "=r"(r2), "=r"(r3) : "r"(addr));
}
__device__ __forceinline__ void mma_bf16(float* c, const uint32_t* a, const uint32_t* b) {
    asm volatile("mma.sync.aligned.m16n8k16.row.col.f32.bf16.bf16.f32 "
                 "{%0,%1,%2,%3}, {%4,%5,%6,%7}, {%8,%9}, {%0,%1,%2,%3};"
                 : "+f"(c[0]), "+f"(c[1]), "+f"(c[2]), "+f"(c[3])
                 : "r"(a[0]), "r"(a[1]), "r"(a[2]), "r"(a[3]), "r"(b[0]), "r"(b[1]));
}

__global__ __launch_bounds__(256, 2) void gemm_mma_kernel(const float* __restrict__ x) {
    extern __shared__ char smem[];
    const uint32_t sb = smem_u32(smem);
    const int tid  = threadIdx.x;
    const int wid  = tid >> 5;
    const int lane = tid & 31;
    const int row0 = blockIdx.x * 128;

    const int wm = wid & 1;
    const int wn = wid >> 1;

    const int lr = tid >> 1;
    const int lh = tid & 1;
    int grow_ld = row0 + lr;
    if (grow_ld >= M_NODES) grow_ld = 0;   // clamp: finite garbage, discarded at store
    const float4* __restrict__ xrow = (const float4*)(x + (size_t)grow_ld * K_DIM);
    const uint4* __restrict__ wt_hi = (const uint4*)g_Wt_hi;
    const uint4* __restrict__ wt_lo = (const uint4*)g_Wt_lo;

    const int a_row = wm * 64 + (lane & 15);
    const int a_kbl = (lane & 16);
    const int b_row = wn * 32 + (lane & 7) + ((lane & 16) ? 8 : 0);
    const int b_kbl = (lane & 8) ? 16 : 0;

    float acc[4][4][4];
#pragma unroll
    for (int mi = 0; mi < 4; mi++)
#pragma unroll
        for (int ni = 0; ni < 4; ni++)
#pragma unroll
            for (int i = 0; i < 4; i++) acc[mi][ni][i] = 0.f;

    for (int c = 0; c < K_DIM / KC; c++) {
        const int k0 = c * KC;
        // ---- A: load 32 f32, split to bf16 hi/lo, store swizzled ----
        {
            const float4* xr = xrow + ((k0 + lh * 32) >> 2);
            float4 fr[8];
#pragma unroll
            for (int j = 0; j < 8; j++) fr[j] = xr[j];
            const float* f = (const float*)fr;
#pragma unroll
            for (int j = 0; j < 4; j++) {
                uint32_t ph[4], pl[4];
#pragma unroll
                for (int i = 0; i < 4; i++) {
                    float f0 = f[j * 8 + 2 * i], f1 = f[j * 8 + 2 * i + 1];
                    __nv_bfloat16 h0 = __float2bfloat16_rn(f0);
                    __nv_bfloat16 h1 = __float2bfloat16_rn(f1);
                    __nv_bfloat162 hp = __halves2bfloat162(h0, h1);
                    __nv_bfloat162 lp = __halves2bfloat162(
                        __float2bfloat16_rn(f0 - __bfloat162float(h0)),
                        __float2bfloat16_rn(f1 - __bfloat162float(h1)));
                    ph[i] = *(uint32_t*)&hp;
                    pl[i] = *(uint32_t*)&lp;
                }
                uint32_t off = SW128((uint32_t)(lr * 128 + lh * 64 + j * 16));
                *(uint4*)(smem + SA_HI + off) = make_uint4(ph[0], ph[1], ph[2], ph[3]);
                *(uint4*)(smem + SA_LO + off) = make_uint4(pl[0], pl[1], pl[2], pl[3]);
            }
        }
        // ---- B tiles (L2-resident after first wave) ----
        {
            const int gbase = (lr * K_DIM + k0 + lh * 32) >> 3;
#pragma unroll
            for (int j = 0; j < 4; j++) {
                uint32_t off = SW128((uint32_t)(lr * 128 + lh * 64 + j * 16));
                *(uint4*)(smem + SB_HI + off) = wt_hi[gbase + j];
                *(uint4*)(smem + SB_LO + off) = wt_lo[gbase + j];
            }
        }
        __syncthreads();

        // ---- Compute: 4 k16 steps ----
#pragma unroll
        for (int ks = 0; ks < 4; ks++) {
            const int kbase = ks * 32;
            uint32_t bh[8], bl[8];
#pragma unroll
            for (int g = 0; g < 2; g++) {
                uint32_t off = SW128((uint32_t)((b_row + g * 16) * 128 + kbase + b_kbl));
                ldsm_x4(bh[g * 4 + 0], bh[g * 4 + 1], bh[g * 4 + 2], bh[g * 4 + 3],
                        sb + SB_HI + off);
                ldsm_x4(bl[g * 4 + 0], bl[g * 4 + 1], bl[g * 4 + 2], bl[g * 4 + 3],
                        sb + SB_LO + off);
            }
#pragma unroll
            for (int mi = 0; mi < 4; mi++) {
                uint32_t ah[4], al[4];
                uint32_t off = SW128((uint32_t)((a_row + mi * 16) * 128 + kbase + a_kbl));
                ldsm_x4(ah[0], ah[1], ah[2], ah[3], sb + SA_HI + off);
                ldsm_x4(al[0], al[1], al[2], al[3], sb + SA_LO + off);
#pragma unroll
                for (int ni = 0; ni < 4; ni++) {
                    mma_bf16(acc[mi][ni], ah, &bh[ni * 2]);
                    mma_bf16(acc[mi][ni], ah, &bl[ni * 2]);
                    mma_bf16(acc[mi][ni], al, &bh[ni * 2]);
                }
            }
        }
        __syncthreads();
    }

    const int er = lane >> 2;
    const int ec = (lane & 3) * 2;
#pragma unroll
    for (int mi = 0; mi < 4; mi++) {
        int grow = row0 + wm * 64 + mi * 16 + er;
#pragma unroll
        for (int ni = 0; ni < 4; ni++) {
            int col = wn * 32 + ni * 8 + ec;
            if (grow < M_NODES)
                *(float2*)(g_h + (size_t)grow * N_DIM + col) =
                    make_float2(acc[mi][ni][0], acc[mi][ni][1]);
            if (grow + 8 < M_NODES)
                *(float2*)(g_h + (size_t)(grow + 8) * N_DIM + col) =
                    make_float2(acc[mi][ni][2], acc[mi][ni][3]);
        }
    }
}

// ---------------------------------------------------------------------------
// CSR build: zero -> count(+slot) -> fused scan -> fill (atomic-free, ILP 8)
// ---------------------------------------------------------------------------
__global__ __launch_bounds__(256) void zero_kernel() {
    int i = blockIdx.x * blockDim.x + threadIdx.x;
    g_count[i] = 0;
    if (i == 0) g_total = 0;
}

// 4 edges per thread; slot = position of edge within its row.
__global__ __launch_bounds__(256) void count_kernel(const int* __restrict__ rows) {
    int i0 = (blockIdx.x * blockDim.x + threadIdx.x) * 4;
    if (i0 + 3 < N_EDGES) {
        int4 r4 = *(const int4*)(rows + i0);
        g_slot[i0 + 0] = atomicAdd(&g_count[r4.x], 1);
        g_slot[i0 + 1] = atomicAdd(&g_count[r4.y], 1);
        g_slot[i0 + 2] = atomicAdd(&g_count[r4.z], 1);
        g_slot[i0 + 3] = atomicAdd(&g_count[r4.w], 1);
    } else {
        for (int j = 0; j < 4 && i0 + j < N_EDGES; j++)
            g_slot[i0 + j] = atomicAdd(&g_count[rows[i0 + j]], 1);
    }
}

// Single-pass scan: block-local inclusive scan + atomic block base.
// CSR ranges are disjoint (ordering across blocks irrelevant for gather).
__global__ __launch_bounds__(256) void scan_fused_kernel() {
    __shared__ int s[256];
    __shared__ int base_sh;
    int t = threadIdx.x, b = blockIdx.x;
    int i = b * 256 + t;
    int c = g_count[i];
    s[t] = c;
    __syncthreads();
    int v = c;
#pragma unroll
    for (int d = 1; d < 256; d <<= 1) {
        int add = (t >= d) ? s[t - d] : 0;
        __syncthreads();
        v += add;
        s[t] = v;
        __syncthreads();
    }
    if (t == 255) base_sh = atomicAdd(&g_total, v);
    __syncthreads();
    g_off[i] = base_sh + v - c;      // exclusive within block + block base
}

// Atomic-free fill: pos = off[row] + slot[edge]. 8 edges per thread, MLP 8.
__global__ __launch_bounds__(256) void fill_kernel(const int* __restrict__ rows,
                                                   const int* __restrict__ cols,
                                                   const float* __restrict__ vals) {
    int i0 = (blockIdx.x * blockDim.x + threadIdx.x) * 8;
    if (i0 + 7 < N_EDGES) {
        int4   ra = *(const int4*)(rows + i0);
        int4   rb = *(const int4*)(rows + i0 + 4);
        int4   ca = *(const int4*)(cols + i0);
        int4   cb = *(const int4*)(cols + i0 + 4);
        float4 va = *(const float4*)(vals + i0);
        float4 vb = *(const float4*)(vals + i0 + 4);
        int4   sa = *(const int4*)(g_slot + i0);
        int4   sb4 = *(const int4*)(g_slot + i0 + 4);
        // 8 independent off loads (MLP 8)
        int o0 = g_off[ra.x], o1 = g_off[ra.y], o2 = g_off[ra.z], o3 = g_off[ra.w];
        int o4 = g_off[rb.x], o5 = g_off[rb.y], o6 = g_off[rb.z], o7 = g_off[rb.w];
        g_csr[o0 + sa.x]  = ((uint64_t)__float_as_uint(va.x) << 32) | (uint32_t)ca.x;
        g_csr[o1 + sa.y]  = ((uint64_t)__float_as_uint(va.y) << 32) | (uint32_t)ca.y;
        g_csr[o2 + sa.z]  = ((uint64_t)__float_as_uint(va.z) << 32) | (uint32_t)ca.z;
        g_csr[o3 + sa.w]  = ((uint64_t)__float_as_uint(va.w) << 32) | (uint32_t)ca.w;
        g_csr[o4 + sb4.x] = ((uint64_t)__float_as_uint(vb.x) << 32) | (uint32_t)cb.x;
        g_csr[o5 + sb4.y] = ((uint64_t)__float_as_uint(vb.y) << 32) | (uint32_t)cb.y;
        g_csr[o6 + sb4.z] = ((uint64_t)__float_as_uint(vb.z) << 32) | (uint32_t)cb.z;
        g_csr[o7 + sb4.w] = ((uint64_t)__float_as_uint(vb.w) << 32) | (uint32_t)cb.w;
    } else {
        for (int j = 0; j < 8 && i0 + j < N_EDGES; j++) {
            int i = i0 + j;
            int pos = g_off[rows[i]] + g_slot[i];
            g_csr[pos] = ((uint64_t)__float_as_uint(vals[i]) << 32) | (uint32_t)cols[i];
        }
    }
}

// ---------------------------------------------------------------------------
// Gather: one warp per node, smem edge broadcast, x4 unroll, fused relu.
// (at L2 traffic floor — unchanged)
// ---------------------------------------------------------------------------
__global__ __launch_bounds__(256) void gather_kernel(float* __restrict__ out) {
    __shared__ uint64_t ebuf[8][32];
    const int wib  = threadIdx.x >> 5;
    const int lane = threadIdx.x & 31;
    const int warp = (blockIdx.x * blockDim.x + threadIdx.x) >> 5;
    if (warp >= M_NODES) return;

    const int start = g_off[warp];
    const int deg   = g_count[warp];
    const float4* __restrict__ h4 = (const float4*)g_h;

    float4 acc0 = make_float4(0.f, 0.f, 0.f, 0.f);
    float4 acc1 = make_float4(0.f, 0.f, 0.f, 0.f);

    for (int base = 0; base < deg; base += 32) {
        int lim = deg - base;
        if (lim > 32) lim = 32;
        __syncwarp();
        if (lane < lim) ebuf[wib][lane] = g_csr[start + base + lane];
        __syncwarp();

        int j = 0;
        for (; j + 4 <= lim; j += 4) {
            uint64_t e0 = ebuf[wib][j + 0];
            uint64_t e1 = ebuf[wib][j + 1];
            uint64_t e2 = ebuf[wib][j + 2];
            uint64_t e3 = ebuf[wib][j + 3];
            float4 h0 = h4[(size_t)(uint32_t)e0 * 32 + lane];
            float4 h1 = h4[(size_t)(uint32_t)e1 * 32 + lane];
            float4 h2 = h4[(size_t)(uint32_t)e2 * 32 + lane];
            float4 h3 = h4[(size_t)(uint32_t)e3 * 32 + lane];
            float v0 = __uint_as_float((uint32_t)(e0 >> 32));
            float v1 = __uint_as_float((uint32_t)(e1 >> 32));
            float v2 = __uint_as_float((uint32_t)(e2 >> 32));
            float v3 = __uint_as_float((uint32_t)(e3 >> 32));
            acc0.x = fmaf(v0, h0.x, acc0.x); acc0.y = fmaf(v0, h0.y, acc0.y);
            acc0.z = fmaf(v0, h0.z, acc0.z); acc0.w = fmaf(v0, h0.w, acc0.w);
            acc1.x = fmaf(v1, h1.x, acc1.x); acc1.y = fmaf(v1, h1.y, acc1.y);
            acc1.z = fmaf(v1, h1.z, acc1.z); acc1.w = fmaf(v1, h1.w, acc1.w);
            acc0.x = fmaf(v2, h2.x, acc0.x); acc0.y = fmaf(v2, h2.y, acc0.y);
            acc0.z = fmaf(v2, h2.z, acc0.z); acc0.w = fmaf(v2, h2.w, acc0.w);
            acc1.x = fmaf(v3, h3.x, acc1.x); acc1.y = fmaf(v3, h3.y, acc1.y);
            acc1.z = fmaf(v3, h3.z, acc1.z); acc1.w = fmaf(v3, h3.w, acc1.w);
        }
        for (; j < lim; j++) {
            uint64_t e = ebuf[wib][j];
            float4 hv = h4[(size_t)(uint32_t)e * 32 + lane];
            float  v  = __uint_as_float((uint32_t)(e >> 32));
            acc0.x = fmaf(v, hv.x, acc0.x); acc0.y = fmaf(v, hv.y, acc0.y);
            acc0.z = fmaf(v, hv.z, acc0.z); acc0.w = fmaf(v, hv.w, acc0.w);
        }
    }

    float4 r;
    r.x = fmaxf(acc0.x + acc1.x, 0.f);
    r.y = fmaxf(acc0.y + acc1.y, 0.f);
    r.z = fmaxf(acc0.z + acc1.z, 0.f);
    r.w = fmaxf(acc0.w + acc1.w, 0.f);
    *(float4*)(out + (size_t)warp * N_DIM + lane * 4) = r;
}

extern "C" void kernel_launch(void* const* d_in, const int* in_sizes, int n_in,
                              void* d_out, int out_size) {
    const float* x    = (const float*)d_in[0];
    const float* W    = (const float*)d_in[1];
    const int*   rows = (const int*)d_in[2];
    const int*   cols = (const int*)d_in[3];
    const float* vals = (const float*)d_in[4];
    float* out = (float*)d_out;

    cudaFuncSetAttribute(gemm_mma_kernel,
                         cudaFuncAttributeMaxDynamicSharedMemorySize, SMEM_TOTAL);

    // CSR build
    zero_kernel<<<SCAN_BLK, 256>>>();
    count_kernel<<<(N_EDGES / 4 + 255) / 256, 256>>>(rows);
    scan_fused_kernel<<<SCAN_BLK, 256>>>();
    fill_kernel<<<(N_EDGES / 8 + 255) / 256, 256>>>(rows, cols, vals);

    // Dense projection h = x @ W
    wconv_kernel<<<(N_DIM * K_DIM) / 256, 256>>>(W);
    gemm_mma_kernel<<<(M_NODES + 127) / 128, 256, SMEM_TOTAL>>>(x);

    // Aggregate + relu, single write per row
    gather_kernel<<<(M_NODES * 32 + 255) / 256, 256>>>(out);
}

// round 16
// speedup vs baseline: 1.1391x; 1.0866x over previous
#include <cuda_runtime.h>
#include <cuda_bf16.h>
#include <cstdint>

#define M_NODES 100000
#define K_DIM   256
#define N_DIM   128
#define N_EDGES 1600000

#define SCAN_N   100352            // M_NODES padded to 392*256
#define SCAN_BLK 392

// Intermediate h = x @ W (fp32), L2-resident during gather.
__device__ float g_h[(size_t)M_NODES * N_DIM];
// Pre-split, pre-transposed weights: [N=128][K=256] bf16, K-major.
__device__ __nv_bfloat16 g_Wt_hi[(size_t)N_DIM * K_DIM];
__device__ __nv_bfloat16 g_Wt_lo[(size_t)N_DIM * K_DIM];
// CSR scratch
__device__ int      g_count[SCAN_N];
__device__ int      g_off[SCAN_N];
__device__ int      g_slot[N_EDGES];  // edge's slot within its row (from count pass)
__device__ int      g_total;
__device__ uint64_t g_csr[N_EDGES];   // packed {val_bits:32 | col:32}

__device__ __forceinline__ uint32_t smem_u32(const void* p) {
    uint32_t a;
    asm("{ .reg .u64 t; cvta.to.shared.u64 t, %1; cvt.u32.u64 %0, t; }" : "=r"(a) : "l"(p));
    return a;
}
#define SW128(off) ((off) ^ (((off) >> 3) & 0x70))

// ---------------------------------------------------------------------------
// W pre-split: g_Wt_{hi,lo}[n][k] = split(W[k][n])
// ---------------------------------------------------------------------------
__global__ void wconv_kernel(const float* __restrict__ W) {
    int idx = blockIdx.x * blockDim.x + threadIdx.x;   // 0..32767
    int n = idx >> 8, k = idx & 255;
    float w = W[(size_t)k * N_DIM + n];
    __nv_bfloat16 hi = __float2bfloat16_rn(w);
    __nv_bfloat16 lo = __float2bfloat16_rn(w - __bfloat162float(hi));
    g_Wt_hi[idx] = hi;
    g_Wt_lo[idx] = lo;
}

// ---------------------------------------------------------------------------
// mma.sync bf16 GEMM, CTA tile M128xN128, K chunk 64, 3-term split.
// R11 structure (short load->convert window; no cross-MMA register prefetch).
// ---------------------------------------------------------------------------
#define KC 64
#define SA_HI 0
#define SA_LO 16384
#define SB_HI 32768
#define SB_LO 49152
#define SMEM_TOTAL 65536

__device__ __forceinline__ void ldsm_x4(uint32_t& r0, uint32_t& r1,
                                        uint32_t& r2, uint32_t& r3, uint32_t addr) {
    asm volatile("ldmatrix.sync.aligned.m8n8.x4.shared.b16 {%0,%1,%2,%3}, [%4];"
                 : "=r"(r0), "=r"(r1), "=r"(r2), "=r"(r3) : "r"(addr));
}
__device__ __forceinline__ void mma_bf16(float* c, const uint32_t* a, const uint32_t* b) {
    asm volatile("mma.sync.aligned.m16n8k16.row.col.f32.bf16.bf16.f32 "
                 "{%0,%1,%2,%3}, {%4,%5,%6,%7}, {%8,%9}, {%0,%1,%2,%3};"
                 : "+f"(c[0]), "+f"(c[1]), "+f"(c[2]), "+f"(c[3])
                 : "r"(a[0]), "r"(a[1]), "r"(a[2]), "r"(a[3]), "r"(b[0]), "r"(b[1]));
}

__global__ __launch_bounds__(256, 2) void gemm_mma_kernel(const float* __restrict__ x) {
    extern __shared__ char smem[];
    const uint32_t sb = smem_u32(smem);
    const int tid  = threadIdx.x;
    const int wid  = tid >> 5;
    const int lane = tid & 31;
    const int row0 = blockIdx.x * 128;

    const int wm = wid & 1;
    const int wn = wid >> 1;

    const int lr = tid >> 1;
    const int lh = tid & 1;
    int grow_ld = row0 + lr;
    if (grow_ld >= M_NODES) grow_ld = 0;   // clamp: finite garbage, discarded at store
    const float4* __restrict__ xrow = (const float4*)(x + (size_t)grow_ld * K_DIM);
    const uint4* __restrict__ wt_hi = (const uint4*)g_Wt_hi;
    const uint4* __restrict__ wt_lo = (const uint4*)g_Wt_lo;

    const int a_row = wm * 64 + (lane & 15);
    const int a_kbl = (lane & 16);
    const int b_row = wn * 32 + (lane & 7) + ((lane & 16) ? 8 : 0);
    const int b_kbl = (lane & 8) ? 16 : 0;

    float acc[4][4][4];
#pragma unroll
    for (int mi = 0; mi < 4; mi++)
#pragma unroll
        for (int ni = 0; ni < 4; ni++)
#pragma unroll
            for (int i = 0; i < 4; i++) acc[mi][ni][i] = 0.f;

    for (int c = 0; c < K_DIM / KC; c++) {
        const int k0 = c * KC;
        // ---- A: load 32 f32, split to bf16 hi/lo, store swizzled ----
        {
            const float4* xr = xrow + ((k0 + lh * 32) >> 2);
            float4 fr[8];
#pragma unroll
            for (int j = 0; j < 8; j++) fr[j] = xr[j];
            const float* f = (const float*)fr;
#pragma unroll
            for (int j = 0; j < 4; j++) {
                uint32_t ph[4], pl[4];
#pragma unroll
                for (int i = 0; i < 4; i++) {
                    float f0 = f[j * 8 + 2 * i], f1 = f[j * 8 + 2 * i + 1];
                    __nv_bfloat16 h0 = __float2bfloat16_rn(f0);
                    __nv_bfloat16 h1 = __float2bfloat16_rn(f1);
                    __nv_bfloat162 hp = __halves2bfloat162(h0, h1);
                    __nv_bfloat162 lp = __halves2bfloat162(
                        __float2bfloat16_rn(f0 - __bfloat162float(h0)),
                        __float2bfloat16_rn(f1 - __bfloat162float(h1)));
                    ph[i] = *(uint32_t*)&hp;
                    pl[i] = *(uint32_t*)&lp;
                }
                uint32_t off = SW128((uint32_t)(lr * 128 + lh * 64 + j * 16));
                *(uint4*)(smem + SA_HI + off) = make_uint4(ph[0], ph[1], ph[2], ph[3]);
                *(uint4*)(smem + SA_LO + off) = make_uint4(pl[0], pl[1], pl[2], pl[3]);
            }
        }
        // ---- B tiles (L2-resident after first wave) ----
        {
            const int gbase = (lr * K_DIM + k0 + lh * 32) >> 3;
#pragma unroll
            for (int j = 0; j < 4; j++) {
                uint32_t off = SW128((uint32_t)(lr * 128 + lh * 64 + j * 16));
                *(uint4*)(smem + SB_HI + off) = wt_hi[gbase + j];
                *(uint4*)(smem + SB_LO + off) = wt_lo[gbase + j];
            }
        }
        __syncthreads();

        // ---- Compute: 4 k16 steps ----
#pragma unroll
        for (int ks = 0; ks < 4; ks++) {
            const int kbase = ks * 32;
            uint32_t bh[8], bl[8];
#pragma unroll
            for (int g = 0; g < 2; g++) {
                uint32_t off = SW128((uint32_t)((b_row + g * 16) * 128 + kbase + b_kbl));
                ldsm_x4(bh[g * 4 + 0], bh[g * 4 + 1], bh[g * 4 + 2], bh[g * 4 + 3],
                        sb + SB_HI + off);
                ldsm_x4(bl[g * 4 + 0], bl[g * 4 + 1], bl[g * 4 + 2], bl[g * 4 + 3],
                        sb + SB_LO + off);
            }
#pragma unroll
            for (int mi = 0; mi < 4; mi++) {
                uint32_t ah[4], al[4];
                uint32_t off = SW128((uint32_t)((a_row + mi * 16) * 128 + kbase + a_kbl));
                ldsm_x4(ah[0], ah[1], ah[2], ah[3], sb + SA_HI + off);
                ldsm_x4(al[0], al[1], al[2], al[3], sb + SA_LO + off);
#pragma unroll
                for (int ni = 0; ni < 4; ni++) {
                    mma_bf16(acc[mi][ni], ah, &bh[ni * 2]);
                    mma_bf16(acc[mi][ni], ah, &bl[ni * 2]);
                    mma_bf16(acc[mi][ni], al, &bh[ni * 2]);
                }
            }
        }
        __syncthreads();
    }

    const int er = lane >> 2;
    const int ec = (lane & 3) * 2;
#pragma unroll
    for (int mi = 0; mi < 4; mi++) {
        int grow = row0 + wm * 64 + mi * 16 + er;
#pragma unroll
        for (int ni = 0; ni < 4; ni++) {
            int col = wn * 32 + ni * 8 + ec;
            if (grow < M_NODES)
                *(float2*)(g_h + (size_t)grow * N_DIM + col) =
                    make_float2(acc[mi][ni][0], acc[mi][ni][1]);
            if (grow + 8 < M_NODES)
                *(float2*)(g_h + (size_t)(grow + 8) * N_DIM + col) =
                    make_float2(acc[mi][ni][2], acc[mi][ni][3]);
        }
    }
}

// ---------------------------------------------------------------------------
// CSR build: zero -> count(+slot) -> fused scan -> fill (atomic-free, ILP 4)
// ---------------------------------------------------------------------------
__global__ __launch_bounds__(256) void zero_kernel() {
    int i = blockIdx.x * blockDim.x + threadIdx.x;
    g_count[i] = 0;
    if (i == 0) g_total = 0;
}

// 4 edges per thread; slot = position of edge within its row.
__global__ __launch_bounds__(256) void count_kernel(const int* __restrict__ rows) {
    int i0 = (blockIdx.x * blockDim.x + threadIdx.x) * 4;
    if (i0 + 3 < N_EDGES) {
        int4 r4 = *(const int4*)(rows + i0);
        g_slot[i0 + 0] = atomicAdd(&g_count[r4.x], 1);
        g_slot[i0 + 1] = atomicAdd(&g_count[r4.y], 1);
        g_slot[i0 + 2] = atomicAdd(&g_count[r4.z], 1);
        g_slot[i0 + 3] = atomicAdd(&g_count[r4.w], 1);
    } else {
        for (int j = 0; j < 4 && i0 + j < N_EDGES; j++)
            g_slot[i0 + j] = atomicAdd(&g_count[rows[i0 + j]], 1);
    }
}

// Single-pass scan: block-local inclusive scan + atomic block base.
// CSR ranges are disjoint (ordering across blocks irrelevant for gather).
__global__ __launch_bounds__(256) void scan_fused_kernel() {
    __shared__ int s[256];
    __shared__ int base_sh;
    int t = threadIdx.x, b = blockIdx.x;
    int i = b * 256 + t;
    int c = g_count[i];
    s[t] = c;
    __syncthreads();
    int v = c;
#pragma unroll
    for (int d = 1; d < 256; d <<= 1) {
        int add = (t >= d) ? s[t - d] : 0;
        __syncthreads();
        v += add;
        s[t] = v;
        __syncthreads();
    }
    if (t == 255) base_sh = atomicAdd(&g_total, v);
    __syncthreads();
    g_off[i] = base_sh + v - c;      // exclusive within block + block base
}

// Atomic-free fill: pos = off[row] + slot[edge]. 4 edges per thread (ILP 4,
// measured better than ILP 8 -- occupancy covers latency).
__global__ __launch_bounds__(256) void fill_kernel(const int* __restrict__ rows,
                                                   const int* __restrict__ cols,
                                                   const float* __restrict__ vals) {
    int i0 = (blockIdx.x * blockDim.x + threadIdx.x) * 4;
    if (i0 + 3 < N_EDGES) {
        int4   r4 = *(const int4*)(rows + i0);
        int4   c4 = *(const int4*)(cols + i0);
        float4 v4 = *(const float4*)(vals + i0);
        int4   s4 = *(const int4*)(g_slot + i0);
        int o0 = g_off[r4.x], o1 = g_off[r4.y], o2 = g_off[r4.z], o3 = g_off[r4.w];
        g_csr[o0 + s4.x] = ((uint64_t)__float_as_uint(v4.x) << 32) | (uint32_t)c4.x;
        g_csr[o1 + s4.y] = ((uint64_t)__float_as_uint(v4.y) << 32) | (uint32_t)c4.y;
        g_csr[o2 + s4.z] = ((uint64_t)__float_as_uint(v4.z) << 32) | (uint32_t)c4.z;
        g_csr[o3 + s4.w] = ((uint64_t)__float_as_uint(v4.w) << 32) | (uint32_t)c4.w;
    } else {
        for (int j = 0; j < 4 && i0 + j < N_EDGES; j++) {
            int i = i0 + j;
            int pos = g_off[rows[i]] + g_slot[i];
            g_csr[pos] = ((uint64_t)__float_as_uint(vals[i]) << 32) | (uint32_t)cols[i];
        }
    }
}

// ---------------------------------------------------------------------------
// Gather: one warp per node, smem edge broadcast, x4 unroll, fused relu.
// ---------------------------------------------------------------------------
__global__ __launch_bounds__(256) void gather_kernel(float* __restrict__ out) {
    __shared__ uint64_t ebuf[8][32];
    const int wib  = threadIdx.x >> 5;
    const int lane = threadIdx.x & 31;
    const int warp = (blockIdx.x * blockDim.x + threadIdx.x) >> 5;
    if (warp >= M_NODES) return;

    const int start = g_off[warp];
    const int deg   = g_count[warp];
    const float4* __restrict__ h4 = (const float4*)g_h;

    float4 acc0 = make_float4(0.f, 0.f, 0.f, 0.f);
    float4 acc1 = make_float4(0.f, 0.f, 0.f, 0.f);

    for (int base = 0; base < deg; base += 32) {
        int lim = deg - base;
        if (lim > 32) lim = 32;
        __syncwarp();
        if (lane < lim) ebuf[wib][lane] = g_csr[start + base + lane];
        __syncwarp();

        int j = 0;
        for (; j + 4 <= lim; j += 4) {
            uint64_t e0 = ebuf[wib][j + 0];
            uint64_t e1 = ebuf[wib][j + 1];
            uint64_t e2 = ebuf[wib][j + 2];
            uint64_t e3 = ebuf[wib][j + 3];
            float4 h0 = h4[(size_t)(uint32_t)e0 * 32 + lane];
            float4 h1 = h4[(size_t)(uint32_t)e1 * 32 + lane];
            float4 h2 = h4[(size_t)(uint32_t)e2 * 32 + lane];
            float4 h3 = h4[(size_t)(uint32_t)e3 * 32 + lane];
            float v0 = __uint_as_float((uint32_t)(e0 >> 32));
            float v1 = __uint_as_float((uint32_t)(e1 >> 32));
            float v2 = __uint_as_float((uint32_t)(e2 >> 32));
            float v3 = __uint_as_float((uint32_t)(e3 >> 32));
            acc0.x = fmaf(v0, h0.x, acc0.x); acc0.y = fmaf(v0, h0.y, acc0.y);
            acc0.z = fmaf(v0, h0.z, acc0.z); acc0.w = fmaf(v0, h0.w, acc0.w);
            acc1.x = fmaf(v1, h1.x, acc1.x); acc1.y = fmaf(v1, h1.y, acc1.y);
            acc1.z = fmaf(v1, h1.z, acc1.z); acc1.w = fmaf(v1, h1.w, acc1.w);
            acc0.x = fmaf(v2, h2.x, acc0.x); acc0.y = fmaf(v2, h2.y, acc0.y);
            acc0.z = fmaf(v2, h2.z, acc0.z); acc0.w = fmaf(v2, h2.w, acc0.w);
            acc1.x = fmaf(v3, h3.x, acc1.x); acc1.y = fmaf(v3, h3.y, acc1.y);
            acc1.z = fmaf(v3, h3.z, acc1.z); acc1.w = fmaf(v3, h3.w, acc1.w);
        }
        for (; j < lim; j++) {
            uint64_t e = ebuf[wib][j];
            float4 hv = h4[(size_t)(uint32_t)e * 32 + lane];
            float  v  = __uint_as_float((uint32_t)(e >> 32));
            acc0.x = fmaf(v, hv.x, acc0.x); acc0.y = fmaf(v, hv.y, acc0.y);
            acc0.z = fmaf(v, hv.z, acc0.z); acc0.w = fmaf(v, hv.w, acc0.w);
        }
    }

    float4 r;
    r.x = fmaxf(acc0.x + acc1.x, 0.f);
    r.y = fmaxf(acc0.y + acc1.y, 0.f);
    r.z = fmaxf(acc0.z + acc1.z, 0.f);
    r.w = fmaxf(acc0.w + acc1.w, 0.f);
    *(float4*)(out + (size_t)warp * N_DIM + lane * 4) = r;
}

extern "C" void kernel_launch(void* const* d_in, const int* in_sizes, int n_in,
                              void* d_out, int out_size) {
    const float* x    = (const float*)d_in[0];
    const float* W    = (const float*)d_in[1];
    const int*   rows = (const int*)d_in[2];
    const int*   cols = (const int*)d_in[3];
    const float* vals = (const float*)d_in[4];
    float* out = (float*)d_out;

    // Lazy host-side resources (no device memory involved).
    static cudaStream_t s_side = nullptr;
    static cudaEvent_t  ev_fork = nullptr, ev_join = nullptr;
    if (s_side == nullptr) {
        cudaStreamCreateWithFlags(&s_side, cudaStreamNonBlocking);
        cudaEventCreateWithFlags(&ev_fork, cudaEventDisableTiming);
        cudaEventCreateWithFlags(&ev_join, cudaEventDisableTiming);
        cudaFuncSetAttribute(gemm_mma_kernel,
                             cudaFuncAttributeMaxDynamicSharedMemorySize, SMEM_TOTAL);
    }

    // Fork: CSR build (rows/cols/vals) runs concurrently with wconv+GEMM (x, W).
    cudaEventRecord(ev_fork, 0);
    cudaStreamWaitEvent(s_side, ev_fork, 0);

    // Branch A (side stream): CSR build
    zero_kernel<<<SCAN_BLK, 256, 0, s_side>>>();
    count_kernel<<<(N_EDGES / 4 + 255) / 256, 256, 0, s_side>>>(rows);
    scan_fused_kernel<<<SCAN_BLK, 256, 0, s_side>>>();
    fill_kernel<<<(N_EDGES / 4 + 255) / 256, 256, 0, s_side>>>(rows, cols, vals);
    cudaEventRecord(ev_join, s_side);

    // Branch B (main stream): dense projection h = x @ W
    wconv_kernel<<<(N_DIM * K_DIM) / 256, 256>>>(W);
    gemm_mma_kernel<<<(M_NODES + 127) / 128, 256, SMEM_TOTAL>>>(x);

    // Join, then aggregate + relu (single write per row)
    cudaStreamWaitEvent(0, ev_join, 0);
    gather_kernel<<<(M_NODES * 32 + 255) / 256, 256>>>(out);
}

// round 17
// speedup vs baseline: 1.2355x; 1.0847x over previous
#include <cuda_runtime.h>
#include <cuda_fp16.h>
#include <cstdint>

#define M_NODES 100000
#define K_DIM   256
#define N_DIM   128
#define N_EDGES 1600000

#define SCAN_N   100352            // M_NODES padded to 392*256
#define SCAN_BLK 392

// Intermediate h = x @ W (fp32), L2-resident during gather.
__device__ float g_h[(size_t)M_NODES * N_DIM];
// Pre-transposed weight: [N=128][K=256] fp16, K-major (single term).
__device__ __half g_Wt_h[(size_t)N_DIM * K_DIM];
// CSR scratch
__device__ int      g_count[SCAN_N];
__device__ int      g_off[SCAN_N];
__device__ int      g_slot[N_EDGES];  // edge's slot within its row (from count pass)
__device__ int      g_total;
__device__ uint64_t g_csr[N_EDGES];   // packed {val_bits:32 | col:32}

__device__ __forceinline__ uint32_t smem_u32(const void* p) {
    uint32_t a;
    asm("{ .reg .u64 t; cvta.to.shared.u64 t, %1; cvt.u32.u64 %0, t; }" : "=r"(a) : "l"(p));
    return a;
}
#define SW128(off) ((off) ^ (((off) >> 3) & 0x70))

// ---------------------------------------------------------------------------
// W convert: g_Wt_h[n][k] = fp16(W[k][n])   (single term; W-quant error
// ~2^-12 relative dominates the scheme's error budget, ~1e-4 global)
// ---------------------------------------------------------------------------
__global__ void wconv_kernel(const float* __restrict__ W) {
    int idx = blockIdx.x * blockDim.x + threadIdx.x;   // 0..32767
    int n = idx >> 8, k = idx & 255;
    g_Wt_h[idx] = __float2half_rn(W[(size_t)k * N_DIM + n]);
}

// ---------------------------------------------------------------------------
// mma.sync fp16 GEMM, CTA tile M128xN128, K chunk 64, 2-term x split:
// h = (x_hi + x_lo) @ W_fp16. A smem: hi+lo tiles; B smem: single tile.
// ---------------------------------------------------------------------------
#define KC 64
#define SA_HI 0
#define SA_LO 16384
#define SB_H  32768
#define SMEM_TOTAL 49152

__device__ __forceinline__ void ldsm_x4(uint32_t& r0, uint32_t& r1,
                                        uint32_t& r2, uint32_t& r3, uint32_t addr) {
    asm volatile("ldmatrix.sync.aligned.m8n8.x4.shared.b16 {%0,%1,%2,%3}, [%4];"
                 : "=r"(r0), "=r"(r1), "=r"(r2), "=r"(r3) : "r"(addr));
}
__device__ __forceinline__ void mma_f16(float* c, const uint32_t* a, const uint32_t* b) {
    asm volatile("mma.sync.aligned.m16n8k16.row.col.f32.f16.f16.f32 "
                 "{%0,%1,%2,%3}, {%4,%5,%6,%7}, {%8,%9}, {%0,%1,%2,%3};"
                 : "+f"(c[0]), "+f"(c[1]), "+f"(c[2]), "+f"(c[3])
                 : "r"(a[0]), "r"(a[1]), "r"(a[2]), "r"(a[3]), "r"(b[0]), "r"(b[1]));
}

__global__ __launch_bounds__(256, 2) void gemm_mma_kernel(const float* __restrict__ x) {
    extern __shared__ char smem[];
    const uint32_t sb = smem_u32(smem);
    const int tid  = threadIdx.x;
    const int wid  = tid >> 5;
    const int lane = tid & 31;
    const int row0 = blockIdx.x * 128;

    const int wm = wid & 1;
    const int wn = wid >> 1;

    const int lr = tid >> 1;
    const int lh = tid & 1;
    int grow_ld = row0 + lr;
    if (grow_ld >= M_NODES) grow_ld = 0;   // clamp: finite garbage, discarded at store
    const float4* __restrict__ xrow = (const float4*)(x + (size_t)grow_ld * K_DIM);
    const uint4* __restrict__ wt_h = (const uint4*)g_Wt_h;

    const int a_row = wm * 64 + (lane & 15);
    const int a_kbl = (lane & 16);
    const int b_row = wn * 32 + (lane & 7) + ((lane & 16) ? 8 : 0);
    const int b_kbl = (lane & 8) ? 16 : 0;

    float acc[4][4][4];
#pragma unroll
    for (int mi = 0; mi < 4; mi++)
#pragma unroll
        for (int ni = 0; ni < 4; ni++)
#pragma unroll
            for (int i = 0; i < 4; i++) acc[mi][ni][i] = 0.f;

    for (int c = 0; c < K_DIM / KC; c++) {
        const int k0 = c * KC;
        // ---- A: load 32 f32, split to fp16 hi/lo, store swizzled ----
        {
            const float4* xr = xrow + ((k0 + lh * 32) >> 2);
            float4 fr[8];
#pragma unroll
            for (int j = 0; j < 8; j++) fr[j] = xr[j];
            const float* f = (const float*)fr;
#pragma unroll
            for (int j = 0; j < 4; j++) {
                uint32_t ph[4], pl[4];
#pragma unroll
                for (int i = 0; i < 4; i++) {
                    float f0 = f[j * 8 + 2 * i], f1 = f[j * 8 + 2 * i + 1];
                    __half h0 = __float2half_rn(f0);
                    __half h1 = __float2half_rn(f1);
                    __half2 hp = __halves2half2(h0, h1);
                    __half2 lp = __halves2half2(
                        __float2half_rn(f0 - __half2float(h0)),
                        __float2half_rn(f1 - __half2float(h1)));
                    ph[i] = *(uint32_t*)&hp;
                    pl[i] = *(uint32_t*)&lp;
                }
                uint32_t off = SW128((uint32_t)(lr * 128 + lh * 64 + j * 16));
                *(uint4*)(smem + SA_HI + off) = make_uint4(ph[0], ph[1], ph[2], ph[3]);
                *(uint4*)(smem + SA_LO + off) = make_uint4(pl[0], pl[1], pl[2], pl[3]);
            }
        }
        // ---- B tile (single fp16 term; L2-resident after first wave) ----
        {
            const int gbase = (lr * K_DIM + k0 + lh * 32) >> 3;
#pragma unroll
            for (int j = 0; j < 4; j++) {
                uint32_t off = SW128((uint32_t)(lr * 128 + lh * 64 + j * 16));
                *(uint4*)(smem + SB_H + off) = wt_h[gbase + j];
            }
        }
        __syncthreads();

        // ---- Compute: 4 k16 steps, 2 MMA terms ----
#pragma unroll
        for (int ks = 0; ks < 4; ks++) {
            const int kbase = ks * 32;
            uint32_t bh[8];
#pragma unroll
            for (int g = 0; g < 2; g++) {
                uint32_t off = SW128((uint32_t)((b_row + g * 16) * 128 + kbase + b_kbl));
                ldsm_x4(bh[g * 4 + 0], bh[g * 4 + 1], bh[g * 4 + 2], bh[g * 4 + 3],
                        sb + SB_H + off);
            }
#pragma unroll
            for (int mi = 0; mi < 4; mi++) {
                uint32_t ah[4], al[4];
                uint32_t off = SW128((uint32_t)((a_row + mi * 16) * 128 + kbase + a_kbl));
                ldsm_x4(ah[0], ah[1], ah[2], ah[3], sb + SA_HI + off);
                ldsm_x4(al[0], al[1], al[2], al[3], sb + SA_LO + off);
#pragma unroll
                for (int ni = 0; ni < 4; ni++) {
                    mma_f16(acc[mi][ni], ah, &bh[ni * 2]);
                    mma_f16(acc[mi][ni], al, &bh[ni * 2]);
                }
            }
        }
        __syncthreads();
    }

    const int er = lane >> 2;
    const int ec = (lane & 3) * 2;
#pragma unroll
    for (int mi = 0; mi < 4; mi++) {
        int grow = row0 + wm * 64 + mi * 16 + er;
#pragma unroll
        for (int ni = 0; ni < 4; ni++) {
            int col = wn * 32 + ni * 8 + ec;
            if (grow < M_NODES)
                *(float2*)(g_h + (size_t)grow * N_DIM + col) =
                    make_float2(acc[mi][ni][0], acc[mi][ni][1]);
            if (grow + 8 < M_NODES)
                *(float2*)(g_h + (size_t)(grow + 8) * N_DIM + col) =
                    make_float2(acc[mi][ni][2], acc[mi][ni][3]);
        }
    }
}

// ---------------------------------------------------------------------------
// CSR build: zero -> count(+slot) -> fused scan -> fill (atomic-free, ILP 4)
// ---------------------------------------------------------------------------
__global__ __launch_bounds__(256) void zero_kernel() {
    int i = blockIdx.x * blockDim.x + threadIdx.x;
    g_count[i] = 0;
    if (i == 0) g_total = 0;
}

__global__ __launch_bounds__(256) void count_kernel(const int* __restrict__ rows) {
    int i0 = (blockIdx.x * blockDim.x + threadIdx.x) * 4;
    if (i0 + 3 < N_EDGES) {
        int4 r4 = *(const int4*)(rows + i0);
        g_slot[i0 + 0] = atomicAdd(&g_count[r4.x], 1);
        g_slot[i0 + 1] = atomicAdd(&g_count[r4.y], 1);
        g_slot[i0 + 2] = atomicAdd(&g_count[r4.z], 1);
        g_slot[i0 + 3] = atomicAdd(&g_count[r4.w], 1);
    } else {
        for (int j = 0; j < 4 && i0 + j < N_EDGES; j++)
            g_slot[i0 + j] = atomicAdd(&g_count[rows[i0 + j]], 1);
    }
}

__global__ __launch_bounds__(256) void scan_fused_kernel() {
    __shared__ int s[256];
    __shared__ int base_sh;
    int t = threadIdx.x, b = blockIdx.x;
    int i = b * 256 + t;
    int c = g_count[i];
    s[t] = c;
    __syncthreads();
    int v = c;
#pragma unroll
    for (int d = 1; d < 256; d <<= 1) {
        int add = (t >= d) ? s[t - d] : 0;
        __syncthreads();
        v += add;
        s[t] = v;
        __syncthreads();
    }
    if (t == 255) base_sh = atomicAdd(&g_total, v);
    __syncthreads();
    g_off[i] = base_sh + v - c;      // exclusive within block + block base
}

__global__ __launch_bounds__(256) void fill_kernel(const int* __restrict__ rows,
                                                   const int* __restrict__ cols,
                                                   const float* __restrict__ vals) {
    int i0 = (blockIdx.x * blockDim.x + threadIdx.x) * 4;
    if (i0 + 3 < N_EDGES) {
        int4   r4 = *(const int4*)(rows + i0);
        int4   c4 = *(const int4*)(cols + i0);
        float4 v4 = *(const float4*)(vals + i0);
        int4   s4 = *(const int4*)(g_slot + i0);
        int o0 = g_off[r4.x], o1 = g_off[r4.y], o2 = g_off[r4.z], o3 = g_off[r4.w];
        g_csr[o0 + s4.x] = ((uint64_t)__float_as_uint(v4.x) << 32) | (uint32_t)c4.x;
        g_csr[o1 + s4.y] = ((uint64_t)__float_as_uint(v4.y) << 32) | (uint32_t)c4.y;
        g_csr[o2 + s4.z] = ((uint64_t)__float_as_uint(v4.z) << 32) | (uint32_t)c4.z;
        g_csr[o3 + s4.w] = ((uint64_t)__float_as_uint(v4.w) << 32) | (uint32_t)c4.w;
    } else {
        for (int j = 0; j < 4 && i0 + j < N_EDGES; j++) {
            int i = i0 + j;
            int pos = g_off[rows[i]] + g_slot[i];
            g_csr[pos] = ((uint64_t)__float_as_uint(vals[i]) << 32) | (uint32_t)cols[i];
        }
    }
}

// ---------------------------------------------------------------------------
// Gather: one warp per node, smem edge broadcast, x4 unroll, fused relu.
// ---------------------------------------------------------------------------
__global__ __launch_bounds__(256) void gather_kernel(float* __restrict__ out) {
    __shared__ uint64_t ebuf[8][32];
    const int wib  = threadIdx.x >> 5;
    const int lane = threadIdx.x & 31;
    const int warp = (blockIdx.x * blockDim.x + threadIdx.x) >> 5;
    if (warp >= M_NODES) return;

    const int start = g_off[warp];
    const int deg   = g_count[warp];
    const float4* __restrict__ h4 = (const float4*)g_h;

    float4 acc0 = make_float4(0.f, 0.f, 0.f, 0.f);
    float4 acc1 = make_float4(0.f, 0.f, 0.f, 0.f);

    for (int base = 0; base < deg; base += 32) {
        int lim = deg - base;
        if (lim > 32) lim = 32;
        __syncwarp();
        if (lane < lim) ebuf[wib][lane] = g_csr[start + base + lane];
        __syncwarp();

        int j = 0;
        for (; j + 4 <= lim; j += 4) {
            uint64_t e0 = ebuf[wib][j + 0];
            uint64_t e1 = ebuf[wib][j + 1];
            uint64_t e2 = ebuf[wib][j + 2];
            uint64_t e3 = ebuf[wib][j + 3];
            float4 h0 = h4[(size_t)(uint32_t)e0 * 32 + lane];
            float4 h1 = h4[(size_t)(uint32_t)e1 * 32 + lane];
            float4 h2 = h4[(size_t)(uint32_t)e2 * 32 + lane];
            float4 h3 = h4[(size_t)(uint32_t)e3 * 32 + lane];
            float v0 = __uint_as_float((uint32_t)(e0 >> 32));
            float v1 = __uint_as_float((uint32_t)(e1 >> 32));
            float v2 = __uint_as_float((uint32_t)(e2 >> 32));
            float v3 = __uint_as_float((uint32_t)(e3 >> 32));
            acc0.x = fmaf(v0, h0.x, acc0.x); acc0.y = fmaf(v0, h0.y, acc0.y);
            acc0.z = fmaf(v0, h0.z, acc0.z); acc0.w = fmaf(v0, h0.w, acc0.w);
            acc1.x = fmaf(v1, h1.x, acc1.x); acc1.y = fmaf(v1, h1.y, acc1.y);
            acc1.z = fmaf(v1, h1.z, acc1.z); acc1.w = fmaf(v1, h1.w, acc1.w);
            acc0.x = fmaf(v2, h2.x, acc0.x); acc0.y = fmaf(v2, h2.y, acc0.y);
            acc0.z = fmaf(v2, h2.z, acc0.z); acc0.w = fmaf(v2, h2.w, acc0.w);
            acc1.x = fmaf(v3, h3.x, acc1.x); acc1.y = fmaf(v3, h3.y, acc1.y);
            acc1.z = fmaf(v3, h3.z, acc1.z); acc1.w = fmaf(v3, h3.w, acc1.w);
        }
        for (; j < lim; j++) {
            uint64_t e = ebuf[wib][j];
            float4 hv = h4[(size_t)(uint32_t)e * 32 + lane];
            float  v  = __uint_as_float((uint32_t)(e >> 32));
            acc0.x = fmaf(v, hv.x, acc0.x); acc0.y = fmaf(v, hv.y, acc0.y);
            acc0.z = fmaf(v, hv.z, acc0.z); acc0.w = fmaf(v, hv.w, acc0.w);
        }
    }

    float4 r;
    r.x = fmaxf(acc0.x + acc1.x, 0.f);
    r.y = fmaxf(acc0.y + acc1.y, 0.f);
    r.z = fmaxf(acc0.z + acc1.z, 0.f);
    r.w = fmaxf(acc0.w + acc1.w, 0.f);
    *(float4*)(out + (size_t)warp * N_DIM + lane * 4) = r;
}

extern "C" void kernel_launch(void* const* d_in, const int* in_sizes, int n_in,
                              void* d_out, int out_size) {
    const float* x    = (const float*)d_in[0];
    const float* W    = (const float*)d_in[1];
    const int*   rows = (const int*)d_in[2];
    const int*   cols = (const int*)d_in[3];
    const float* vals = (const float*)d_in[4];
    float* out = (float*)d_out;

    // Lazy host-side resources (no device memory involved).
    static cudaStream_t s_side = nullptr;
    static cudaEvent_t  ev_fork = nullptr, ev_join = nullptr;
    if (s_side == nullptr) {
        cudaStreamCreateWithFlags(&s_side, cudaStreamNonBlocking);
        cudaEventCreateWithFlags(&ev_fork, cudaEventDisableTiming);
        cudaEventCreateWithFlags(&ev_join, cudaEventDisableTiming);
        cudaFuncSetAttribute(gemm_mma_kernel,
                             cudaFuncAttributeMaxDynamicSharedMemorySize, SMEM_TOTAL);
    }

    // Fork: CSR build (rows/cols/vals) runs concurrently with wconv+GEMM (x, W).
    cudaEventRecord(ev_fork, 0);
    cudaStreamWaitEvent(s_side, ev_fork, 0);

    // Branch A (side stream): CSR build
    zero_kernel<<<SCAN_BLK, 256, 0, s_side>>>();
    count_kernel<<<(N_EDGES / 4 + 255) / 256, 256, 0, s_side>>>(rows);
    scan_fused_kernel<<<SCAN_BLK, 256, 0, s_side>>>();
    fill_kernel<<<(N_EDGES / 4 + 255) / 256, 256, 0, s_side>>>(rows, cols, vals);
    cudaEventRecord(ev_join, s_side);

    // Branch B (main stream): dense projection h = x @ W
    wconv_kernel<<<(N_DIM * K_DIM) / 256, 256>>>(W);
    gemm_mma_kernel<<<(M_NODES + 127) / 128, 256, SMEM_TOTAL>>>(x);

    // Join, then aggregate + relu (single write per row)
    cudaStreamWaitEvent(0, ev_join, 0);
    gather_kernel<<<(M_NODES * 32 + 255) / 256, 256>>>(out);
}